// round 5
// baseline (speedup 1.0000x reference)
#include <cuda_runtime.h>

#define U_NUM_C 50000
#define I_NUM_C 50000
#define NNZ_C   2500000

// Scratch (static device globals — no allocation allowed)
__device__ float g_QKu[(size_t)U_NUM_C * 128];        // [Qu | Ku] per user row, 25.6 MB
__device__ float g_QKi[(size_t)I_NUM_C * 128];        // [Qi | Ki] per item row, 25.6 MB
__device__ float g_ev [(size_t)2 * NNZ_C];            // exp-values per edge (ui then iu), 20 MB
__device__ float g_sum[U_NUM_C + I_NUM_C + 64];       // segment sums (users then items), pad for fused zeroing

// ---------------------------------------------------------------------------
// Projection tables: for every row x of [user_embed; item_embed] compute
// [x@Wq^T + bq | x@Wk^T + bk]  -> g_QKu / g_QKi  (128 outputs per row).
// Also zeroes this block's 64-entry slice of g_sum (fused former zero_kernel).
// Block: 256 threads, 64 rows per block. Thread owns output column j = tid&127
// and half of the rows; weight column j held in registers, embed tile in smem.
// ---------------------------------------------------------------------------
__global__ __launch_bounds__(256) void table_kernel(
    const float* __restrict__ user_embed, const float* __restrict__ item_embed,
    const float* __restrict__ Wq, const float* __restrict__ bq,
    const float* __restrict__ Wk, const float* __restrict__ bk,
    int u_num, int i_num)
{
    __shared__ float e_sh[64][64];   // 16 KB embed tile
    const int tid   = threadIdx.x;
    const int j     = tid & 127;
    const int rhalf = tid >> 7;      // 0 or 1
    const int total = u_num + i_num;
    const long long row0 = (long long)blockIdx.x * 64;

    // fused segment-sum zeroing: block b owns g_sum[b*64 .. b*64+63]
    if (tid < 64) {
        long long z = row0 + tid;
        if (z < total) g_sum[z] = 0.0f;
    }

    // weight column j (row j of Wq or Wk is contiguous in global memory)
    const float* wrow = (j < 64) ? (Wq + (size_t)j * 64) : (Wk + (size_t)(j - 64) * 64);
    const float  bias = (j < 64) ? bq[j] : bk[j - 64];
    float4 w4[16];
#pragma unroll
    for (int i = 0; i < 16; i++) w4[i] = reinterpret_cast<const float4*>(wrow)[i];

    // cooperative tile load: 64 rows x 16 float4
    for (int t = tid; t < 64 * 16; t += 256) {
        int r  = t >> 4;
        int c4 = t & 15;
        long long gr = row0 + r;
        float4 val = make_float4(0.f, 0.f, 0.f, 0.f);
        if (gr < u_num)
            val = reinterpret_cast<const float4*>(user_embed + gr * 64)[c4];
        else if (gr < total)
            val = reinterpret_cast<const float4*>(item_embed + (gr - u_num) * 64)[c4];
        reinterpret_cast<float4*>(&e_sh[r][0])[c4] = val;
    }
    __syncthreads();

#pragma unroll 4
    for (int rr = 0; rr < 32; rr++) {
        int r = rhalf + 2 * rr;                 // warp-uniform row -> broadcast LDS
        float acc = bias;
        const float4* e4 = reinterpret_cast<const float4*>(&e_sh[r][0]);
#pragma unroll
        for (int i = 0; i < 16; i++) {
            float4 e = e4[i];
            acc += e.x * w4[i].x + e.y * w4[i].y + e.z * w4[i].z + e.w * w4[i].w;
        }
        long long gr = row0 + r;
        if (gr < u_num)            g_QKu[gr * 128 + j] = acc;
        else if (gr < total)       g_QKi[(gr - u_num) * 128 + j] = acc;
    }
}

// ---------------------------------------------------------------------------
// Edge pass: 8 lanes per edge. Compute both 64-d dots,
//   w_ui = <Qu[r], Ki[c]>,  w_iu = <Qi[c], Ku[r]>
// then ev = exp(w) / (-log u)   (== exp((w - log(-log u))/tau), tau=1),
// store ev and atomically accumulate the segment sums.
// Stride-8 float4 chunk assignment -> every warp-LDG covers full 128B lines.
// ---------------------------------------------------------------------------
__device__ __forceinline__ float neg_log_accurate(float u) {
    // -log(u), accurate for u near 1 regardless of fast-math remapping.
    return (u > 0.5f) ? (-log1pf(u - 1.0f)) : (-__logf(u));
}

__global__ __launch_bounds__(256) void edge_kernel(
    const int* __restrict__ rows, const int* __restrict__ cols,
    const float* __restrict__ u_ui, const float* __restrict__ u_iu,
    int nnz, int u_num)
{
    const int tid = threadIdx.x;
    const int sub = tid & 7;
    const int e   = blockIdx.x * 32 + (tid >> 3);
    const int ee  = (e < nnz) ? e : (nnz - 1);   // clamp: keep shfl convergent

    const int r = rows[ee];
    const int c = cols[ee];

    // issue the scalar noise load early so it overlaps the shfl chain
    float u_val = 0.5f;
    if (e < nnz) {
        if (sub == 0)      u_val = u_ui[e];
        else if (sub == 4) u_val = u_iu[e];
    }

    const float4* pu = reinterpret_cast<const float4*>(g_QKu) + (size_t)r * 32;
    const float4* pi = reinterpret_cast<const float4*>(g_QKi) + (size_t)c * 32;

    // lane sub handles float4-chunks {sub, sub+8} of each 64-dim half
    float4 a0 = pu[sub],      a1 = pu[sub + 8];    // Qu
    float4 b0 = pu[16 + sub], b1 = pu[24 + sub];   // Ku
    float4 c0 = pi[sub],      c1 = pi[sub + 8];    // Qi
    float4 d0 = pi[16 + sub], d1 = pi[24 + sub];   // Ki

    float s_ui = a0.x * d0.x + a0.y * d0.y + a0.z * d0.z + a0.w * d0.w
               + a1.x * d1.x + a1.y * d1.y + a1.z * d1.z + a1.w * d1.w;
    float s_iu = c0.x * b0.x + c0.y * b0.y + c0.z * b0.z + c0.w * b0.w
               + c1.x * b1.x + c1.y * b1.y + c1.z * b1.z + c1.w * b1.w;

#pragma unroll
    for (int off = 4; off > 0; off >>= 1) {
        s_ui += __shfl_xor_sync(0xffffffffu, s_ui, off);
        s_iu += __shfl_xor_sync(0xffffffffu, s_iu, off);
    }

    if (e < nnz) {
        if (sub == 0) {
            float ev = __expf(s_ui) / neg_log_accurate(u_val);
            g_ev[e] = ev;
            atomicAdd(&g_sum[r], ev);
        } else if (sub == 4) {
            float ev = __expf(s_iu) / neg_log_accurate(u_val);
            g_ev[(size_t)nnz + e] = ev;
            atomicAdd(&g_sum[u_num + c], ev);
        }
    }
}

// ---------------------------------------------------------------------------
// Normalize: out[e] = ev[e] / sum[seg], 4 edges per thread (vectorized).
// ---------------------------------------------------------------------------
__global__ __launch_bounds__(256) void norm_kernel(
    const int* __restrict__ rows, const int* __restrict__ cols,
    float* __restrict__ out, int nnz, int u_num)
{
    int e4 = blockIdx.x * blockDim.x + threadIdx.x;   // index in float4 units
    int e  = e4 * 4;
    if (e + 3 < nnz) {
        int4   rr = reinterpret_cast<const int4*>(rows)[e4];
        int4   cc = reinterpret_cast<const int4*>(cols)[e4];
        float4 vu = reinterpret_cast<const float4*>(g_ev)[e4];
        float4 vi = reinterpret_cast<const float4*>(g_ev + (size_t)nnz)[e4];
        float4 ou, oi;
        ou.x = vu.x / g_sum[rr.x];  ou.y = vu.y / g_sum[rr.y];
        ou.z = vu.z / g_sum[rr.z];  ou.w = vu.w / g_sum[rr.w];
        oi.x = vi.x / g_sum[u_num + cc.x];  oi.y = vi.y / g_sum[u_num + cc.y];
        oi.z = vi.z / g_sum[u_num + cc.z];  oi.w = vi.w / g_sum[u_num + cc.w];
        reinterpret_cast<float4*>(out)[e4]                 = ou;
        reinterpret_cast<float4*>(out + (size_t)nnz)[e4]   = oi;
    } else {
        for (int k = e; k < nnz; k++) {
            out[k]               = g_ev[k]               / g_sum[rows[k]];
            out[(size_t)nnz + k] = g_ev[(size_t)nnz + k] / g_sum[u_num + cols[k]];
        }
    }
}

// ---------------------------------------------------------------------------
extern "C" void kernel_launch(void* const* d_in, const int* in_sizes, int n_in,
                              void* d_out, int out_size)
{
    const float* user_embed = (const float*)d_in[0];
    const float* item_embed = (const float*)d_in[1];
    const float* Wq         = (const float*)d_in[2];
    const float* bq         = (const float*)d_in[3];
    const float* Wk         = (const float*)d_in[4];
    const float* bk         = (const float*)d_in[5];
    const int*   rows       = (const int*)d_in[6];
    const int*   cols       = (const int*)d_in[7];
    const float* u_ui       = (const float*)d_in[8];
    const float* u_iu       = (const float*)d_in[9];
    float*       out        = (float*)d_out;

    const int u_num = in_sizes[0] / 64;
    const int i_num = in_sizes[1] / 64;
    const int nnz   = in_sizes[6];

    table_kernel<<<(u_num + i_num + 63) / 64, 256>>>(user_embed, item_embed,
                                                     Wq, bq, Wk, bk, u_num, i_num);
    edge_kernel <<<(nnz + 31) / 32, 256>>>(rows, cols, u_ui, u_iu, nnz, u_num);

    int n4 = (nnz + 3) / 4;
    norm_kernel <<<(n4 + 255) / 256, 256>>>(rows, cols, out, nnz, u_num);
}

// round 15
// speedup vs baseline: 1.0419x; 1.0419x over previous
#include <cuda_runtime.h>
#include <cuda_fp16.h>

#define U_NUM_C 50000
#define I_NUM_C 50000
#define NNZ_C   2500000

// Scratch (static device globals — no allocation allowed)
__device__ __half g_QKu[(size_t)U_NUM_C * 128];       // [Qu | Ku] per user row, fp16, 12.8 MB
__device__ __half g_QKi[(size_t)I_NUM_C * 128];       // [Qi | Ki] per item row, fp16, 12.8 MB
__device__ float  g_ev [(size_t)2 * NNZ_C];           // exp-values per edge (ui then iu), 20 MB
__device__ float  g_sum[U_NUM_C + I_NUM_C + 64];      // segment sums (users then items)

// ---------------------------------------------------------------------------
// Projection tables -> fp16. Block: 256 threads, 64 rows. Thread owns column
// j = tid&127 (weight col in regs) and computes 32 rows with FOUR independent
// accumulators to break the FFMA dependency chain (was: 1 chain, lat-bound).
// Also zeroes this block's 64-entry slice of g_sum.
// ---------------------------------------------------------------------------
__global__ __launch_bounds__(256) void table_kernel(
    const float* __restrict__ user_embed, const float* __restrict__ item_embed,
    const float* __restrict__ Wq, const float* __restrict__ bq,
    const float* __restrict__ Wk, const float* __restrict__ bk,
    int u_num, int i_num)
{
    __shared__ float e_sh[64][64];   // 16 KB embed tile
    const int tid   = threadIdx.x;
    const int j     = tid & 127;
    const int rhalf = tid >> 7;      // 0 or 1
    const int total = u_num + i_num;
    const long long row0 = (long long)blockIdx.x * 64;

    // fused segment-sum zeroing: block b owns g_sum[b*64 .. b*64+63]
    if (tid < 64) {
        long long z = row0 + tid;
        if (z < total) g_sum[z] = 0.0f;
    }

    const float* wrow = (j < 64) ? (Wq + (size_t)j * 64) : (Wk + (size_t)(j - 64) * 64);
    const float  bias = (j < 64) ? bq[j] : bk[j - 64];
    float4 w4[16];
#pragma unroll
    for (int i = 0; i < 16; i++) w4[i] = reinterpret_cast<const float4*>(wrow)[i];

    // cooperative tile load: 64 rows x 16 float4
    for (int t = tid; t < 64 * 16; t += 256) {
        int r  = t >> 4;
        int c4 = t & 15;
        long long gr = row0 + r;
        float4 val = make_float4(0.f, 0.f, 0.f, 0.f);
        if (gr < u_num)
            val = reinterpret_cast<const float4*>(user_embed + gr * 64)[c4];
        else if (gr < total)
            val = reinterpret_cast<const float4*>(item_embed + (gr - u_num) * 64)[c4];
        reinterpret_cast<float4*>(&e_sh[r][0])[c4] = val;
    }
    __syncthreads();

#pragma unroll 2
    for (int rr = 0; rr < 32; rr++) {
        int r = rhalf + 2 * rr;                 // warp-uniform row -> broadcast LDS
        const float4* e4 = reinterpret_cast<const float4*>(&e_sh[r][0]);
        float a0 = 0.f, a1 = 0.f, a2 = 0.f, a3 = 0.f;   // 4 independent chains
#pragma unroll
        for (int i = 0; i < 16; i++) {
            float4 e = e4[i];
            a0 = fmaf(e.x, w4[i].x, a0);
            a1 = fmaf(e.y, w4[i].y, a1);
            a2 = fmaf(e.z, w4[i].z, a2);
            a3 = fmaf(e.w, w4[i].w, a3);
        }
        float acc = (bias + a0) + (a1 + (a2 + a3));
        long long gr = row0 + r;
        if (gr < u_num)            g_QKu[gr * 128 + j] = __float2half_rn(acc);
        else if (gr < total)       g_QKi[(gr - u_num) * 128 + j] = __float2half_rn(acc);
    }
}

// ---------------------------------------------------------------------------
// fp16 8-element dot with fp32 accumulation
// ---------------------------------------------------------------------------
__device__ __forceinline__ float dot8h(uint4 x, uint4 y) {
    const __half2* hx = reinterpret_cast<const __half2*>(&x);
    const __half2* hy = reinterpret_cast<const __half2*>(&y);
    float s0 = 0.f, s1 = 0.f;
#pragma unroll
    for (int k = 0; k < 4; k++) {
        float2 fx = __half22float2(hx[k]);
        float2 fy = __half22float2(hy[k]);
        s0 = fmaf(fx.x, fy.x, s0);
        s1 = fmaf(fx.y, fy.y, s1);
    }
    return s0 + s1;
}

__device__ __forceinline__ float neg_log_accurate(float u) {
    // -log(u), accurate for u near 1 regardless of fast-math remapping.
    return (u > 0.5f) ? (-log1pf(u - 1.0f)) : (-__logf(u));
}

// ---------------------------------------------------------------------------
// Edge pass: 8 lanes per edge, fp16 gathers (512 B/edge total).
//   w_ui = <Qu[r], Ki[c]>,  w_iu = <Qi[c], Ku[r]>
// ev = exp(w) / (-log u)  (== exp((w - log(-log u))/tau), tau=1)
// ---------------------------------------------------------------------------
__global__ __launch_bounds__(256) void edge_kernel(
    const int* __restrict__ rows, const int* __restrict__ cols,
    const float* __restrict__ u_ui, const float* __restrict__ u_iu,
    int nnz, int u_num)
{
    const int tid = threadIdx.x;
    const int sub = tid & 7;
    const int e   = blockIdx.x * 32 + (tid >> 3);
    const int ee  = (e < nnz) ? e : (nnz - 1);   // clamp: keep shfl convergent

    const int r = rows[ee];
    const int c = cols[ee];

    // issue the scalar noise load early so it overlaps the gathers + shfl chain
    float u_val = 0.5f;
    if (e < nnz) {
        if (sub == 0)      u_val = u_ui[e];
        else if (sub == 4) u_val = u_iu[e];
    }

    // combined row = 128 halves = 16 uint4 chunks; chunks 0-7 = Q, 8-15 = K
    const uint4* pu = reinterpret_cast<const uint4*>(g_QKu + (size_t)r * 128);
    const uint4* pi = reinterpret_cast<const uint4*>(g_QKi + (size_t)c * 128);

    uint4 qu = pu[sub];      // Qu chunk (8 halves)
    uint4 ku = pu[8 + sub];  // Ku chunk
    uint4 qi = pi[sub];      // Qi chunk
    uint4 ki = pi[8 + sub];  // Ki chunk

    float s_ui = dot8h(qu, ki);
    float s_iu = dot8h(qi, ku);

#pragma unroll
    for (int off = 4; off > 0; off >>= 1) {
        s_ui += __shfl_xor_sync(0xffffffffu, s_ui, off);
        s_iu += __shfl_xor_sync(0xffffffffu, s_iu, off);
    }

    if (e < nnz) {
        if (sub == 0) {
            float ev = __expf(s_ui) / neg_log_accurate(u_val);
            g_ev[e] = ev;
            atomicAdd(&g_sum[r], ev);
        } else if (sub == 4) {
            float ev = __expf(s_iu) / neg_log_accurate(u_val);
            g_ev[(size_t)nnz + e] = ev;
            atomicAdd(&g_sum[u_num + c], ev);
        }
    }
}

// ---------------------------------------------------------------------------
// Normalize: out[e] = ev[e] / sum[seg], 4 edges per thread (vectorized).
// ---------------------------------------------------------------------------
__global__ __launch_bounds__(256) void norm_kernel(
    const int* __restrict__ rows, const int* __restrict__ cols,
    float* __restrict__ out, int nnz, int u_num)
{
    int e4 = blockIdx.x * blockDim.x + threadIdx.x;   // index in float4 units
    int e  = e4 * 4;
    if (e + 3 < nnz) {
        int4   rr = reinterpret_cast<const int4*>(rows)[e4];
        int4   cc = reinterpret_cast<const int4*>(cols)[e4];
        float4 vu = reinterpret_cast<const float4*>(g_ev)[e4];
        float4 vi = reinterpret_cast<const float4*>(g_ev + (size_t)nnz)[e4];
        float4 ou, oi;
        ou.x = vu.x / g_sum[rr.x];  ou.y = vu.y / g_sum[rr.y];
        ou.z = vu.z / g_sum[rr.z];  ou.w = vu.w / g_sum[rr.w];
        oi.x = vi.x / g_sum[u_num + cc.x];  oi.y = vi.y / g_sum[u_num + cc.y];
        oi.z = vi.z / g_sum[u_num + cc.z];  oi.w = vi.w / g_sum[u_num + cc.w];
        reinterpret_cast<float4*>(out)[e4]                 = ou;
        reinterpret_cast<float4*>(out + (size_t)nnz)[e4]   = oi;
    } else {
        for (int k = e; k < nnz; k++) {
            out[k]               = g_ev[k]               / g_sum[rows[k]];
            out[(size_t)nnz + k] = g_ev[(size_t)nnz + k] / g_sum[u_num + cols[k]];
        }
    }
}

// ---------------------------------------------------------------------------
extern "C" void kernel_launch(void* const* d_in, const int* in_sizes, int n_in,
                              void* d_out, int out_size)
{
    const float* user_embed = (const float*)d_in[0];
    const float* item_embed = (const float*)d_in[1];
    const float* Wq         = (const float*)d_in[2];
    const float* bq         = (const float*)d_in[3];
    const float* Wk         = (const float*)d_in[4];
    const float* bk         = (const float*)d_in[5];
    const int*   rows       = (const int*)d_in[6];
    const int*   cols       = (const int*)d_in[7];
    const float* u_ui       = (const float*)d_in[8];
    const float* u_iu       = (const float*)d_in[9];
    float*       out        = (float*)d_out;

    const int u_num = in_sizes[0] / 64;
    const int i_num = in_sizes[1] / 64;
    const int nnz   = in_sizes[6];

    table_kernel<<<(u_num + i_num + 63) / 64, 256>>>(user_embed, item_embed,
                                                     Wq, bq, Wk, bk, u_num, i_num);
    edge_kernel <<<(nnz + 31) / 32, 256>>>(rows, cols, u_ui, u_iu, nnz, u_num);

    int n4 = (nnz + 3) / 4;
    norm_kernel <<<(n4 + 255) / 256, 256>>>(rows, cols, out, nnz, u_num);
}